// round 13
// baseline (speedup 1.0000x reference)
#include <cuda_runtime.h>
#include <math.h>
#include <stdint.h>

// ---------------------------------------------------------------------------
// Problem constants
// ---------------------------------------------------------------------------
#define B_   4
#define N_   2048
#define D_   768
#define H_   12
#define HD_  64
#define M_   (B_ * N_)             // 8192
#define QKV_COLS (3 * D_)          // 2304

// Scratch (alloc-free rule)
__device__ float g_qkv[(size_t)M_ * QKV_COLS];     // perm8 layout on d
__device__ float g_att[(size_t)M_ * D_];           // perm8 layout on d
__device__ float g_xr[(size_t)M_ * D_];            // tf32-rounded X, perm8 on k
__device__ float g_wqkvT[(size_t)QKV_COLS * D_];   // [N][K], perm8 on k
__device__ float g_wprojT[(size_t)D_ * D_];        // [N][K], perm8 on k

// perm within each 8-group: d -> (d&3)*2 + ((d>>2)&1)

// ---------------------------------------------------------------------------
// tf32 helpers (legacy mma path — harness targets sm_100 base, no tcgen05)
// ---------------------------------------------------------------------------
__device__ __forceinline__ float tff(float x) {
    float r;
    asm("{ .reg .b32 t; cvt.rna.tf32.f32 t, %1; mov.b32 %0, t; }" : "=f"(r) : "f"(x));
    return r;
}

__device__ __forceinline__ float ex2(float x) {
    float y;
    asm("ex2.approx.ftz.f32 %0, %1;" : "=f"(y) : "f"(x));
    return y;
}

__device__ __forceinline__ void mma_tf32(float* c, const uint32_t* a, const uint32_t* b) {
    asm volatile(
        "mma.sync.aligned.m16n8k8.row.col.f32.tf32.tf32.f32 "
        "{%0,%1,%2,%3}, {%4,%5,%6,%7}, {%8,%9}, {%0,%1,%2,%3};"
        : "+f"(c[0]), "+f"(c[1]), "+f"(c[2]), "+f"(c[3])
        : "r"(a[0]), "r"(a[1]), "r"(a[2]), "r"(a[3]), "r"(b[0]), "r"(b[1]));
}

__device__ __forceinline__ void cpa16(uint32_t dst, const float* src) {
    asm volatile("cp.async.ca.shared.global [%0], [%1], 16;"
                 :: "r"(dst), "l"(src) : "memory");
}
__device__ __forceinline__ void cpa_commit() {
    asm volatile("cp.async.commit_group;" ::: "memory");
}
template<int NN>
__device__ __forceinline__ void cpa_wait() {
    asm volatile("cp.async.wait_group %0;" :: "n"(NN) : "memory");
}

__device__ __forceinline__ uint32_t smem_u32(const void* p) {
    uint32_t a;
    asm("{ .reg .u64 t; cvta.to.shared.u64 t, %1; cvt.u32.u64 %0, t; }" : "=r"(a) : "l"(p));
    return a;
}

// ---------------------------------------------------------------------------
// tf32 round + perm8 interleave (X): 8 floats per thread
// ---------------------------------------------------------------------------
__global__ __launch_bounds__(256) void round_perm(
    const float* __restrict__ in, float* __restrict__ out, int n8)
{
    const int i = blockIdx.x * 256 + threadIdx.x;
    if (i < n8) {
        float4 a = ((const float4*)in)[2 * i];
        float4 b = ((const float4*)in)[2 * i + 1];
        float4 o0 = make_float4(tff(a.x), tff(b.x), tff(a.y), tff(b.y));
        float4 o1 = make_float4(tff(a.z), tff(b.z), tff(a.w), tff(b.w));
        ((float4*)out)[2 * i]     = o0;
        ((float4*)out)[2 * i + 1] = o1;
    }
}

// ---------------------------------------------------------------------------
// Weight transpose + round + perm8 on k: out[N][Kperm] = round(in[K][N]*s)
// ---------------------------------------------------------------------------
__global__ __launch_bounds__(256) void transpose_k(
    const float* __restrict__ in, float* __restrict__ out, int K, int N,
    int qrows, float qscale)
{
    __shared__ float t[32][33];
    const int kb = blockIdx.y * 32, nb = blockIdx.x * 32;
    const int x = threadIdx.x, y = threadIdx.y;
    #pragma unroll
    for (int i = 0; i < 32; i += 8)
        t[y + i][x] = in[(size_t)(kb + y + i) * N + nb + x];
    __syncthreads();
    const int k  = kb + x;
    const int kp = (k & ~7) | (((k & 3) << 1) | ((k >> 2) & 1));
    #pragma unroll
    for (int i = 0; i < 32; i += 8) {
        const int n = nb + y + i;
        const float s = (n < qrows) ? qscale : 1.0f;
        out[(size_t)n * K + kp] = tff(t[x][y + i] * s);
    }
}

// ---------------------------------------------------------------------------
// tf32 GEMM on perm8 inputs (unchanged from R12 win): fragment-major smem fed
// by cp.async 3-stage ring. 128x128 CTA tile, BK=32, 256 threads.
// ---------------------------------------------------------------------------
#define FF_STAGE 8256
#define FF_SMEM (3 * FF_STAGE * 4)

template<bool BIAS, bool ROUND, bool PERMOUT>
__global__ __launch_bounds__(256, 2) void gemm_ff(
    const float* __restrict__ A, const float* __restrict__ WT,
    const float* __restrict__ bias, float* __restrict__ C,
    int N, int K)
{
    extern __shared__ float smf[];
    const uint32_t sb4 = smem_u32(smf);

    const int tid  = threadIdx.x;
    const int lane = tid & 31;
    const int wid  = tid >> 5;
    const int g    = lane >> 2;
    const int tg   = lane & 3;
    const int wm   = wid & 3;
    const int wn   = wid >> 2;
    const int row0 = blockIdx.y * 128;
    const int col0 = blockIdx.x * 128;
    const int KT   = K / 32;

    float acc[2][8][4];
    #pragma unroll
    for (int mt = 0; mt < 2; mt++)
        #pragma unroll
        for (int nt = 0; nt < 8; nt++)
            #pragma unroll
            for (int i = 0; i < 4; i++) acc[mt][nt][i] = 0.f;

    const int lrow = tid >> 3;
    const int lkq  = tid & 7;
    const int ks0  = lkq >> 1;
    const int m0   = lkq & 1;
    const int kA   = 8 * ks0 + 4 * m0;

    const float* Ap = A  + (size_t)(row0 + lrow) * K + kA;
    const float* Bp = WT + (size_t)(col0 + lrow) * K + kA;

    const int dstA0 = ks0 * 1032 + lrow * 8 + 4 * m0;

    #define ISSUE_G(t_) do {                                                 \
        const uint32_t sbase_ = sb4 + ((t_) % 3) * (FF_STAGE * 4);           \
        const size_t koff_ = (size_t)(t_) * 32;                             \
        _Pragma("unroll")                                                    \
        for (int i_ = 0; i_ < 4; i_++) {                                     \
            cpa16(sbase_ + (dstA0 + i_ * 256) * 4,                           \
                  Ap + (size_t)(i_ * 32) * K + koff_);                       \
            cpa16(sbase_ + (4128 + dstA0 + i_ * 256) * 4,                    \
                  Bp + (size_t)(i_ * 32) * K + koff_);                       \
        }                                                                    \
        cpa_commit();                                                        \
    } while (0)

    ISSUE_G(0);
    if (KT > 1) ISSUE_G(1);

    for (int t = 0; t < KT; t++) {
        if (t + 1 < KT) cpa_wait<1>(); else cpa_wait<0>();
        __syncthreads();

        if (t + 2 < KT) ISSUE_G(t + 2);

        const float2* As2 = (const float2*)(smf + (t % 3) * FF_STAGE);
        const float2* Bs2 = As2 + 2064;

        #pragma unroll
        for (int ks = 0; ks < 4; ks++) {
            const float2* Ak = As2 + ks * 516;
            const float2* Bk = Bs2 + ks * 516;
            uint32_t af[2][4];
            #pragma unroll
            for (int mt = 0; mt < 2; mt++) {
                const int r = wm * 32 + mt * 16 + g;
                float2 v1 = Ak[r * 4 + tg];
                float2 v2 = Ak[(r + 8) * 4 + tg];
                af[mt][0] = __float_as_uint(v1.x);
                af[mt][1] = __float_as_uint(v2.x);
                af[mt][2] = __float_as_uint(v1.y);
                af[mt][3] = __float_as_uint(v2.y);
            }
            #pragma unroll
            for (int nt = 0; nt < 8; nt++) {
                const int c = wn * 64 + nt * 8 + g;
                float2 w = Bk[c * 4 + tg];
                uint32_t bf[2] = { __float_as_uint(w.x), __float_as_uint(w.y) };
                mma_tf32(acc[0][nt], af[0], bf);
                mma_tf32(acc[1][nt], af[1], bf);
            }
        }
    }
    #undef ISSUE_G

    const int dl = 2 * tg;
    const int p0 = ((dl & 3) << 1) + (dl >> 2);
    const int p1 = (((dl + 1) & 3) << 1) + ((dl + 1) >> 2);

    #pragma unroll
    for (int mt = 0; mt < 2; mt++) {
        const int r_lo = row0 + wm * 32 + mt * 16 + g;
        const int r_hi = r_lo + 8;
        #pragma unroll
        for (int nt = 0; nt < 8; nt++) {
            const int c = col0 + wn * 64 + nt * 8 + 2 * tg;
            float2 v0 = make_float2(acc[mt][nt][0], acc[mt][nt][1]);
            float2 v1 = make_float2(acc[mt][nt][2], acc[mt][nt][3]);
            if (BIAS) {
                float2 bb = *(const float2*)&bias[c];
                v0.x += bb.x; v0.y += bb.y;
                v1.x += bb.x; v1.y += bb.y;
            }
            if (ROUND) {
                v0.x = tff(v0.x); v0.y = tff(v0.y);
                v1.x = tff(v1.x); v1.y = tff(v1.y);
            }
            if (PERMOUT) {
                const int cg = c & ~7;
                C[(size_t)r_lo * N + cg + p0] = v0.x;
                C[(size_t)r_lo * N + cg + p1] = v0.y;
                C[(size_t)r_hi * N + cg + p0] = v1.x;
                C[(size_t)r_hi * N + cg + p1] = v1.y;
            } else {
                *(float2*)&C[(size_t)r_lo * N + c] = v0;
                *(float2*)&C[(size_t)r_hi * N + c] = v1;
            }
        }
    }
}

// ---------------------------------------------------------------------------
// Flash attention: 64-column KV tiles (halved softmax fixed cost), 2-stage
// cp.async ring, perm8 inputs, Q fragments in regs, raw-P PV.
// smem (words): Ps 8x1032=8256 @0; K 2x(64x72) @8256; V 2x(64x72) @17472.
// Two barriers per iter: one after wait (data ready), one before issuing
// into the stage just read (readers done).
// ---------------------------------------------------------------------------
#define QPL   1032
#define PS_OFF 0
#define KS_OFF 8256
#define KS_STRIDE 4608
#define VS_OFF 17472
#define VS_STRIDE 4608
#define LDK_  72
#define LDV_  72
#define QROWS 128
#define NTILES (N_ / 64)            // 32
#define AT_SMEM ((VS_OFF + 2 * VS_STRIDE) * 4)   // 106752 B

__global__ __launch_bounds__(256, 2) void attn_tc(
    const float* __restrict__ qkv, float* __restrict__ out)
{
    extern __shared__ float sm[];
    const uint32_t sb4 = smem_u32(sm);

    const int tid  = threadIdx.x;
    const int lane = tid & 31;
    const int wid  = tid >> 5;
    const int g    = lane >> 2;
    const int tg   = lane & 3;
    const int qb   = blockIdx.x;            // 0..15
    const int bh   = blockIdx.y;            // 0..47
    const int b    = bh / H_;
    const int h    = bh % H_;

    const size_t base = (size_t)b * N_ * QKV_COLS;
    const int qoff = h * HD_;
    const int koff = D_ + h * HD_;
    const int voff = 2 * D_ + h * HD_;

    // cp.async loader mapping: 4 rows (cr0 + 16i), 16B chunk at col cd
    const int cr0 = tid >> 4;                // 0..15
    const int cd  = (tid & 15) * 4;          // 0..60

    const float* tp = qkv + base + (size_t)cr0 * QKV_COLS;
    const size_t TILE_STEP = (size_t)64 * QKV_COLS;

    #define ISSUE_TILE(ptr_, ss_) do {                                       \
        const uint32_t kd_ = sb4 + (KS_OFF + (ss_) * KS_STRIDE) * 4;         \
        const uint32_t vd_ = sb4 + (VS_OFF + (ss_) * VS_STRIDE) * 4;         \
        _Pragma("unroll")                                                    \
        for (int i_ = 0; i_ < 4; i_++) {                                     \
            const float* r_ = (ptr_) + (size_t)(16 * i_) * QKV_COLS;         \
            cpa16(kd_ + ((cr0 + 16 * i_) * LDK_ + cd) * 4, r_ + koff + cd);  \
            cpa16(vd_ + ((cr0 + 16 * i_) * LDV_ + cd) * 4, r_ + voff + cd);  \
        }                                                                    \
        cpa_commit();                                                        \
    } while (0)

    ISSUE_TILE(tp, 0);
    ISSUE_TILE(tp + TILE_STEP, 1);
    const float* tp2 = tp + 2 * TILE_STEP;

    // ---- Q fragments to registers (perm layout: pair adjacent) ----
    const int r_lo = wid * 16 + g;
    const int r_hi = r_lo + 8;
    uint32_t qf[8][4];
    {
        const float* qlo = qkv + base + (size_t)(qb * QROWS + r_lo) * QKV_COLS + qoff;
        const float* qhi = qkv + base + (size_t)(qb * QROWS + r_hi) * QKV_COLS + qoff;
        #pragma unroll
        for (int ks = 0; ks < 8; ks++) {
            float2 q0 = *(const float2*)&qlo[8 * ks + 2 * tg];
            float2 q1 = *(const float2*)&qhi[8 * ks + 2 * tg];
            qf[ks][0] = __float_as_uint(q0.x);
            qf[ks][2] = __float_as_uint(q0.y);
            qf[ks][1] = __float_as_uint(q1.x);
            qf[ks][3] = __float_as_uint(q1.y);
        }
    }

    const int dd0 = 2 * tg, dd1 = 2 * tg + 1;
    const int poff0 = (dd0 & 3) * 2 + (dd0 >> 2);
    const int poff1 = (dd1 & 3) * 2 + (dd1 >> 2);
    const int pg = ((g & 3) << 1) | (g >> 2);

    float O[8][4];
    #pragma unroll
    for (int nt = 0; nt < 8; nt++)
        #pragma unroll
        for (int i = 0; i < 4; i++) O[nt][i] = 0.f;
    float m_lo = -INFINITY, m_hi = -INFINITY, l_lo = 0.f, l_hi = 0.f;

    for (int t = 0; t < NTILES; t++) {
        const int ss = t & 1;
        if (t == NTILES - 1) cpa_wait<0>(); else cpa_wait<1>();
        __syncthreads();

        const float* Kst = sm + KS_OFF + ss * KS_STRIDE;
        const float* Vst = sm + VS_OFF + ss * VS_STRIDE;

        // ---- S = Q @ K^T (64 cols) ----
        float s[8][4];
        #pragma unroll
        for (int nt = 0; nt < 8; nt++)
            #pragma unroll
            for (int i = 0; i < 4; i++) s[nt][i] = 0.f;

        #pragma unroll
        for (int ks = 0; ks < 8; ks++) {
            const float* Kp = Kst + 8 * ks + 2 * tg;
            #pragma unroll
            for (int nt = 0; nt < 8; nt++) {
                float2 kf = *(const float2*)&Kp[(nt * 8 + g) * LDK_];
                uint32_t bf[2] = { __float_as_uint(kf.x), __float_as_uint(kf.y) };
                mma_tf32(s[nt], qf[ks], bf);
            }
        }

        // ---- online softmax (log2 domain) over 64 columns ----
        float rmx_lo = -INFINITY, rmx_hi = -INFINITY;
        #pragma unroll
        for (int nt = 0; nt < 8; nt++) {
            rmx_lo = fmaxf(rmx_lo, fmaxf(s[nt][0], s[nt][1]));
            rmx_hi = fmaxf(rmx_hi, fmaxf(s[nt][2], s[nt][3]));
        }
        rmx_lo = fmaxf(rmx_lo, __shfl_xor_sync(0xffffffffu, rmx_lo, 1));
        rmx_lo = fmaxf(rmx_lo, __shfl_xor_sync(0xffffffffu, rmx_lo, 2));
        rmx_hi = fmaxf(rmx_hi, __shfl_xor_sync(0xffffffffu, rmx_hi, 1));
        rmx_hi = fmaxf(rmx_hi, __shfl_xor_sync(0xffffffffu, rmx_hi, 2));

        const float mn_lo = fmaxf(m_lo, rmx_lo);
        const float mn_hi = fmaxf(m_hi, rmx_hi);
        const float sc_lo = ex2(m_lo - mn_lo);
        const float sc_hi = ex2(m_hi - mn_hi);

        float rs_lo = 0.f, rs_hi = 0.f;
        #pragma unroll
        for (int nt = 0; nt < 8; nt++) {
            s[nt][0] = ex2(s[nt][0] - mn_lo);
            s[nt][1] = ex2(s[nt][1] - mn_lo);
            s[nt][2] = ex2(s[nt][2] - mn_hi);
            s[nt][3] = ex2(s[nt][3] - mn_hi);
            rs_lo += s[nt][0] + s[nt][1];
            rs_hi += s[nt][2] + s[nt][3];
        }
        rs_lo += __shfl_xor_sync(0xffffffffu, rs_lo, 1);
        rs_lo += __shfl_xor_sync(0xffffffffu, rs_lo, 2);
        rs_hi += __shfl_xor_sync(0xffffffffu, rs_hi, 1);
        rs_hi += __shfl_xor_sync(0xffffffffu, rs_hi, 2);

        l_lo = l_lo * sc_lo + rs_lo;   m_lo = mn_lo;
        l_hi = l_hi * sc_hi + rs_hi;   m_hi = mn_hi;

        #pragma unroll
        for (int nt = 0; nt < 8; nt++) {
            O[nt][0] *= sc_lo; O[nt][1] *= sc_lo;
            O[nt][2] *= sc_hi; O[nt][3] *= sc_hi;
        }

        // ---- store P raw (fragment-major planes, warp-private rows) ----
        #pragma unroll
        for (int nt = 0; nt < 8; nt++) {
            float* Pp = sm + PS_OFF + nt * QPL;
            Pp[r_lo * 8 + poff0] = s[nt][0];
            Pp[r_lo * 8 + poff1] = s[nt][1];
            Pp[r_hi * 8 + poff0] = s[nt][2];
            Pp[r_hi * 8 + poff1] = s[nt][3];
        }
        __syncwarp();

        // ---- O += P @ V (k = 64 rows) ----
        #pragma unroll
        for (int ks = 0; ks < 8; ks++) {
            uint32_t pa[4];
            {
                const float* Pp = sm + PS_OFF + ks * QPL;
                float2 t0 = *(const float2*)&Pp[r_lo * 8 + tg * 2];
                float2 t1 = *(const float2*)&Pp[r_hi * 8 + tg * 2];
                pa[0] = __float_as_uint(t0.x); pa[2] = __float_as_uint(t0.y);
                pa[1] = __float_as_uint(t1.x); pa[3] = __float_as_uint(t1.y);
            }
            const float* Vp  = Vst + (ks * 8 + tg) * LDV_;
            const float* Vp4 = Vp + 4 * LDV_;
            #pragma unroll
            for (int nt = 0; nt < 8; nt++) {
                uint32_t bv[2] = { __float_as_uint(Vp[nt * 8 + pg]),
                                   __float_as_uint(Vp4[nt * 8 + pg]) };
                mma_tf32(O[nt], pa, bv);
            }
        }

        // all warps done reading stage ss -> safe to refill it with tile t+2
        __syncthreads();
        if (t + 2 < NTILES) {
            ISSUE_TILE(tp2, ss);
            tp2 += TILE_STEP;
        }
    }
    #undef ISSUE_TILE

    // ---- finalize + write [B,N,D] perm8'd + tf32-rounded (for proj) ----
    const float il_lo = 1.f / l_lo;
    const float il_hi = 1.f / l_hi;
    const int n_lo = qb * QROWS + r_lo;
    const int n_hi = n_lo + 8;
    #pragma unroll
    for (int nt = 0; nt < 8; nt++) {
        const int cg = h * HD_ + nt * 8;
        float* olo = &out[((size_t)b * N_ + n_lo) * D_ + cg];
        float* ohi = &out[((size_t)b * N_ + n_hi) * D_ + cg];
        olo[poff0] = tff(O[nt][0] * il_lo);
        olo[poff1] = tff(O[nt][1] * il_lo);
        ohi[poff0] = tff(O[nt][2] * il_hi);
        ohi[poff1] = tff(O[nt][3] * il_hi);
    }
}

// ---------------------------------------------------------------------------
// Launch
// ---------------------------------------------------------------------------
extern "C" void kernel_launch(void* const* d_in, const int* in_sizes, int n_in,
                              void* d_out, int out_size)
{
    const float* x      = (const float*)d_in[0];
    const float* w_qkv  = (const float*)d_in[1];
    const float* w_proj = (const float*)d_in[2];
    const float* b_proj = (const float*)d_in[3];
    float* out = (float*)d_out;

    float *qkv, *att, *xr, *wqkvT, *wprojT;
    cudaGetSymbolAddress((void**)&qkv, g_qkv);
    cudaGetSymbolAddress((void**)&att, g_att);
    cudaGetSymbolAddress((void**)&xr, g_xr);
    cudaGetSymbolAddress((void**)&wqkvT, g_wqkvT);
    cudaGetSymbolAddress((void**)&wprojT, g_wprojT);

    cudaFuncSetAttribute(attn_tc, cudaFuncAttributeMaxDynamicSharedMemorySize, AT_SMEM);
    cudaFuncSetAttribute((const void*)gemm_ff<false, true, true>,
                         cudaFuncAttributeMaxDynamicSharedMemorySize, FF_SMEM);
    cudaFuncSetAttribute((const void*)gemm_ff<true, false, false>,
                         cudaFuncAttributeMaxDynamicSharedMemorySize, FF_SMEM);

    const float QSC = 0.18033688011112042f;   // 0.125 * log2(e)

    // 0) pre-round+perm X; transpose+round+perm weights (Q cols pre-scaled)
    round_perm<<<(M_ * D_ / 8 + 255) / 256, 256>>>(x, xr, M_ * D_ / 8);
    transpose_k<<<dim3(QKV_COLS / 32, D_ / 32), dim3(32, 8)>>>(
        w_qkv, wqkvT, D_, QKV_COLS, D_, QSC);
    transpose_k<<<dim3(D_ / 32, D_ / 32), dim3(32, 8)>>>(
        w_proj, wprojT, D_, D_, 0, 1.0f);

    // 1) QKV = Xr @ W_qkv  (rounded + perm8'd output; Q pre-scaled)
    gemm_ff<false, true, true><<<dim3(QKV_COLS / 128, M_ / 128), 256, FF_SMEM>>>(
        xr, wqkvT, nullptr, qkv, QKV_COLS, D_);

    // 2) fused flash attention -> [B,N,D] (rounded + perm8'd)
    attn_tc<<<dim3(N_ / QROWS, B_ * H_), 256, AT_SMEM>>>(qkv, att);

    // 3) OUT = ATT @ W_proj + b  (final output, standard layout)
    gemm_ff<true, false, false><<<dim3(D_ / 128, M_ / 128), 256, FF_SMEM>>>(
        att, wprojT, b_proj, out, D_, D_);
}

// round 14
// speedup vs baseline: 1.0389x; 1.0389x over previous
#include <cuda_runtime.h>
#include <math.h>
#include <stdint.h>

// ---------------------------------------------------------------------------
// Problem constants
// ---------------------------------------------------------------------------
#define B_   4
#define N_   2048
#define D_   768
#define H_   12
#define HD_  64
#define M_   (B_ * N_)             // 8192
#define QKV_COLS (3 * D_)          // 2304

// Scratch (alloc-free rule)
__device__ float g_qkv[(size_t)M_ * QKV_COLS];     // perm8 layout on d
__device__ float g_att[(size_t)M_ * D_];           // perm8 layout on d
__device__ float g_xr[(size_t)M_ * D_];            // tf32-rounded X, perm8 on k
__device__ float g_wqkvT[(size_t)QKV_COLS * D_];   // [N][K], perm8 on k
__device__ float g_wprojT[(size_t)D_ * D_];        // [N][K], perm8 on k

// perm within each 8-group: d -> (d&3)*2 + ((d>>2)&1)

// ---------------------------------------------------------------------------
// tf32 helpers (legacy mma path — harness targets sm_100 base, no tcgen05)
// ---------------------------------------------------------------------------
__device__ __forceinline__ float tff(float x) {
    float r;
    asm("{ .reg .b32 t; cvt.rna.tf32.f32 t, %1; mov.b32 %0, t; }" : "=f"(r) : "f"(x));
    return r;
}

__device__ __forceinline__ float ex2(float x) {
    float y;
    asm("ex2.approx.ftz.f32 %0, %1;" : "=f"(y) : "f"(x));
    return y;
}

__device__ __forceinline__ void mma_tf32(float* c, const uint32_t* a, const uint32_t* b) {
    asm volatile(
        "mma.sync.aligned.m16n8k8.row.col.f32.tf32.tf32.f32 "
        "{%0,%1,%2,%3}, {%4,%5,%6,%7}, {%8,%9}, {%0,%1,%2,%3};"
        : "+f"(c[0]), "+f"(c[1]), "+f"(c[2]), "+f"(c[3])
        : "r"(a[0]), "r"(a[1]), "r"(a[2]), "r"(a[3]), "r"(b[0]), "r"(b[1]));
}

__device__ __forceinline__ void cpa16(uint32_t dst, const float* src) {
    asm volatile("cp.async.ca.shared.global [%0], [%1], 16;"
                 :: "r"(dst), "l"(src) : "memory");
}
__device__ __forceinline__ void cpa_commit() {
    asm volatile("cp.async.commit_group;" ::: "memory");
}
template<int NN>
__device__ __forceinline__ void cpa_wait() {
    asm volatile("cp.async.wait_group %0;" :: "n"(NN) : "memory");
}

__device__ __forceinline__ uint32_t smem_u32(const void* p) {
    uint32_t a;
    asm("{ .reg .u64 t; cvta.to.shared.u64 t, %1; cvt.u32.u64 %0, t; }" : "=r"(a) : "l"(p));
    return a;
}

// ---------------------------------------------------------------------------
// tf32 round + perm8 interleave (X): 8 floats per thread
// ---------------------------------------------------------------------------
__global__ __launch_bounds__(256) void round_perm(
    const float* __restrict__ in, float* __restrict__ out, int n8)
{
    const int i = blockIdx.x * 256 + threadIdx.x;
    if (i < n8) {
        float4 a = ((const float4*)in)[2 * i];
        float4 b = ((const float4*)in)[2 * i + 1];
        float4 o0 = make_float4(tff(a.x), tff(b.x), tff(a.y), tff(b.y));
        float4 o1 = make_float4(tff(a.z), tff(b.z), tff(a.w), tff(b.w));
        ((float4*)out)[2 * i]     = o0;
        ((float4*)out)[2 * i + 1] = o1;
    }
}

// ---------------------------------------------------------------------------
// Weight transpose + round + perm8 on k: out[N][Kperm] = round(in[K][N]*s)
// ---------------------------------------------------------------------------
__global__ __launch_bounds__(256) void transpose_k(
    const float* __restrict__ in, float* __restrict__ out, int K, int N,
    int qrows, float qscale)
{
    __shared__ float t[32][33];
    const int kb = blockIdx.y * 32, nb = blockIdx.x * 32;
    const int x = threadIdx.x, y = threadIdx.y;
    #pragma unroll
    for (int i = 0; i < 32; i += 8)
        t[y + i][x] = in[(size_t)(kb + y + i) * N + nb + x];
    __syncthreads();
    const int k  = kb + x;
    const int kp = (k & ~7) | (((k & 3) << 1) | ((k >> 2) & 1));
    #pragma unroll
    for (int i = 0; i < 32; i += 8) {
        const int n = nb + y + i;
        const float s = (n < qrows) ? qscale : 1.0f;
        out[(size_t)n * K + kp] = tff(t[x][y + i] * s);
    }
}

// ---------------------------------------------------------------------------
// tf32 GEMM on perm8 inputs (unchanged from R12 win): fragment-major smem fed
// by cp.async 3-stage ring. 128x128 CTA tile, BK=32, 256 threads.
// ---------------------------------------------------------------------------
#define FF_STAGE 8256
#define FF_SMEM (3 * FF_STAGE * 4)

template<bool BIAS, bool ROUND, bool PERMOUT>
__global__ __launch_bounds__(256, 2) void gemm_ff(
    const float* __restrict__ A, const float* __restrict__ WT,
    const float* __restrict__ bias, float* __restrict__ C,
    int N, int K)
{
    extern __shared__ float smf[];
    const uint32_t sb4 = smem_u32(smf);

    const int tid  = threadIdx.x;
    const int lane = tid & 31;
    const int wid  = tid >> 5;
    const int g    = lane >> 2;
    const int tg   = lane & 3;
    const int wm   = wid & 3;
    const int wn   = wid >> 2;
    const int row0 = blockIdx.y * 128;
    const int col0 = blockIdx.x * 128;
    const int KT   = K / 32;

    float acc[2][8][4];
    #pragma unroll
    for (int mt = 0; mt < 2; mt++)
        #pragma unroll
        for (int nt = 0; nt < 8; nt++)
            #pragma unroll
            for (int i = 0; i < 4; i++) acc[mt][nt][i] = 0.f;

    const int lrow = tid >> 3;
    const int lkq  = tid & 7;
    const int ks0  = lkq >> 1;
    const int m0   = lkq & 1;
    const int kA   = 8 * ks0 + 4 * m0;

    const float* Ap = A  + (size_t)(row0 + lrow) * K + kA;
    const float* Bp = WT + (size_t)(col0 + lrow) * K + kA;

    const int dstA0 = ks0 * 1032 + lrow * 8 + 4 * m0;

    #define ISSUE_G(t_) do {                                                 \
        const uint32_t sbase_ = sb4 + ((t_) % 3) * (FF_STAGE * 4);           \
        const size_t koff_ = (size_t)(t_) * 32;                             \
        _Pragma("unroll")                                                    \
        for (int i_ = 0; i_ < 4; i_++) {                                     \
            cpa16(sbase_ + (dstA0 + i_ * 256) * 4,                           \
                  Ap + (size_t)(i_ * 32) * K + koff_);                       \
            cpa16(sbase_ + (4128 + dstA0 + i_ * 256) * 4,                    \
                  Bp + (size_t)(i_ * 32) * K + koff_);                       \
        }                                                                    \
        cpa_commit();                                                        \
    } while (0)

    ISSUE_G(0);
    if (KT > 1) ISSUE_G(1);

    for (int t = 0; t < KT; t++) {
        if (t + 1 < KT) cpa_wait<1>(); else cpa_wait<0>();
        __syncthreads();

        if (t + 2 < KT) ISSUE_G(t + 2);

        const float2* As2 = (const float2*)(smf + (t % 3) * FF_STAGE);
        const float2* Bs2 = As2 + 2064;

        #pragma unroll
        for (int ks = 0; ks < 4; ks++) {
            const float2* Ak = As2 + ks * 516;
            const float2* Bk = Bs2 + ks * 516;
            uint32_t af[2][4];
            #pragma unroll
            for (int mt = 0; mt < 2; mt++) {
                const int r = wm * 32 + mt * 16 + g;
                float2 v1 = Ak[r * 4 + tg];
                float2 v2 = Ak[(r + 8) * 4 + tg];
                af[mt][0] = __float_as_uint(v1.x);
                af[mt][1] = __float_as_uint(v2.x);
                af[mt][2] = __float_as_uint(v1.y);
                af[mt][3] = __float_as_uint(v2.y);
            }
            #pragma unroll
            for (int nt = 0; nt < 8; nt++) {
                const int c = wn * 64 + nt * 8 + g;
                float2 w = Bk[c * 4 + tg];
                uint32_t bf[2] = { __float_as_uint(w.x), __float_as_uint(w.y) };
                mma_tf32(acc[0][nt], af[0], bf);
                mma_tf32(acc[1][nt], af[1], bf);
            }
        }
    }
    #undef ISSUE_G

    const int dl = 2 * tg;
    const int p0 = ((dl & 3) << 1) + (dl >> 2);
    const int p1 = (((dl + 1) & 3) << 1) + ((dl + 1) >> 2);

    #pragma unroll
    for (int mt = 0; mt < 2; mt++) {
        const int r_lo = row0 + wm * 32 + mt * 16 + g;
        const int r_hi = r_lo + 8;
        #pragma unroll
        for (int nt = 0; nt < 8; nt++) {
            const int c = col0 + wn * 64 + nt * 8 + 2 * tg;
            float2 v0 = make_float2(acc[mt][nt][0], acc[mt][nt][1]);
            float2 v1 = make_float2(acc[mt][nt][2], acc[mt][nt][3]);
            if (BIAS) {
                float2 bb = *(const float2*)&bias[c];
                v0.x += bb.x; v0.y += bb.y;
                v1.x += bb.x; v1.y += bb.y;
            }
            if (ROUND) {
                v0.x = tff(v0.x); v0.y = tff(v0.y);
                v1.x = tff(v1.x); v1.y = tff(v1.y);
            }
            if (PERMOUT) {
                const int cg = c & ~7;
                C[(size_t)r_lo * N + cg + p0] = v0.x;
                C[(size_t)r_lo * N + cg + p1] = v0.y;
                C[(size_t)r_hi * N + cg + p0] = v1.x;
                C[(size_t)r_hi * N + cg + p1] = v1.y;
            } else {
                *(float2*)&C[(size_t)r_lo * N + c] = v0;
                *(float2*)&C[(size_t)r_hi * N + c] = v1;
            }
        }
    }
}

// ---------------------------------------------------------------------------
// Flash attention: R12 structure (32-col KV tiles) with a DEEPER 4-stage
// cp.async ring + wait_group<2> — each KV load gets two iterations of
// latency slack. perm8 inputs, Q fragments in regs, raw-P PV, perm8 output.
// smem (words): Ps 4x1032=4128 @0; K 4x(32x72)=9216 @4128; V 4x2304 @13344.
// Total 22560 words = 90240 B -> 2 CTAs/SM (regs ~122 also give 2).
// ---------------------------------------------------------------------------
#define QPL   1032
#define PS_OFF 0
#define KS_OFF 4128
#define KS_STRIDE 2304
#define VS_OFF 13344
#define VS_STRIDE 2304
#define LDK_  72
#define LDV_  72
#define QROWS 128
#define NTILES (N_ / 32)            // 64
#define AT_SMEM ((VS_OFF + 4 * VS_STRIDE) * 4)   // 90240 B

__global__ __launch_bounds__(256, 2) void attn_tc(
    const float* __restrict__ qkv, float* __restrict__ out)
{
    extern __shared__ float sm[];
    const uint32_t sb4 = smem_u32(sm);

    const int tid  = threadIdx.x;
    const int lane = tid & 31;
    const int wid  = tid >> 5;
    const int g    = lane >> 2;
    const int tg   = lane & 3;
    const int qb   = blockIdx.x;            // 0..15
    const int bh   = blockIdx.y;            // 0..47
    const int b    = bh / H_;
    const int h    = bh % H_;

    const size_t base = (size_t)b * N_ * QKV_COLS;
    const int qoff = h * HD_;
    const int koff = D_ + h * HD_;
    const int voff = 2 * D_ + h * HD_;

    const int cr0 = tid >> 4;                // 0..15
    const int cd  = (tid & 15) * 4;          // 0..60

    const float* tp = qkv + base + (size_t)cr0 * QKV_COLS;
    const size_t TILE_STEP = (size_t)32 * QKV_COLS;

    #define ISSUE_TILE(ptr_, ss_) do {                                       \
        const float* r1_ = (ptr_) + (size_t)16 * QKV_COLS;                   \
        const uint32_t kd_ = sb4 + (KS_OFF + (ss_) * KS_STRIDE) * 4;         \
        const uint32_t vd_ = sb4 + (VS_OFF + (ss_) * VS_STRIDE) * 4;         \
        cpa16(kd_ + (cr0 * LDK_ + cd) * 4,        (ptr_) + koff + cd);       \
        cpa16(kd_ + ((cr0 + 16) * LDK_ + cd) * 4, r1_ + koff + cd);          \
        cpa16(vd_ + (cr0 * LDV_ + cd) * 4,        (ptr_) + voff + cd);       \
        cpa16(vd_ + ((cr0 + 16) * LDV_ + cd) * 4, r1_ + voff + cd);          \
        cpa_commit();                                                        \
    } while (0)

    // prologue: tiles 0,1,2 into stages 0,1,2
    ISSUE_TILE(tp, 0);
    ISSUE_TILE(tp + TILE_STEP, 1);
    ISSUE_TILE(tp + 2 * TILE_STEP, 2);
    const float* tp3 = tp + 3 * TILE_STEP;   // pointer for tile t+3

    // ---- Q fragments to registers (perm layout: pair adjacent) ----
    const int r_lo = wid * 16 + g;
    const int r_hi = r_lo + 8;
    uint32_t qf[8][4];
    {
        const float* qlo = qkv + base + (size_t)(qb * QROWS + r_lo) * QKV_COLS + qoff;
        const float* qhi = qkv + base + (size_t)(qb * QROWS + r_hi) * QKV_COLS + qoff;
        #pragma unroll
        for (int ks = 0; ks < 8; ks++) {
            float2 q0 = *(const float2*)&qlo[8 * ks + 2 * tg];
            float2 q1 = *(const float2*)&qhi[8 * ks + 2 * tg];
            qf[ks][0] = __float_as_uint(q0.x);
            qf[ks][2] = __float_as_uint(q0.y);
            qf[ks][1] = __float_as_uint(q1.x);
            qf[ks][3] = __float_as_uint(q1.y);
        }
    }

    const int dd0 = 2 * tg, dd1 = 2 * tg + 1;
    const int poff0 = (dd0 & 3) * 2 + (dd0 >> 2);
    const int poff1 = (dd1 & 3) * 2 + (dd1 >> 2);
    const int pg = ((g & 3) << 1) | (g >> 2);

    float O[8][4];
    #pragma unroll
    for (int nt = 0; nt < 8; nt++)
        #pragma unroll
        for (int i = 0; i < 4; i++) O[nt][i] = 0.f;
    float m_lo = -INFINITY, m_hi = -INFINITY, l_lo = 0.f, l_hi = 0.f;

    for (int t = 0; t < NTILES; t++) {
        const int ss = t & 3;
        // pending groups at this point: t, t+1, t+2 (minus tail) — ensure t done
        if (t < NTILES - 2)      cpa_wait<2>();
        else if (t < NTILES - 1) cpa_wait<1>();
        else                     cpa_wait<0>();
        __syncthreads();

        // issue tile t+3 into stage (t+3)&3 == (t-1)&3 — its readers all
        // passed the barrier above.
        if (t + 3 < NTILES) {
            ISSUE_TILE(tp3, (t + 3) & 3);
            tp3 += TILE_STEP;
        }

        const float* Kst = sm + KS_OFF + ss * KS_STRIDE;
        const float* Vst = sm + VS_OFF + ss * VS_STRIDE;

        // ---- S = Q @ K^T (32 cols); K fragments are LDS.64 ----
        float s[4][4];
        #pragma unroll
        for (int nt = 0; nt < 4; nt++)
            #pragma unroll
            for (int i = 0; i < 4; i++) s[nt][i] = 0.f;

        #pragma unroll
        for (int ks = 0; ks < 8; ks++) {
            const float* Kp = Kst + 8 * ks + 2 * tg;
            #pragma unroll
            for (int nt = 0; nt < 4; nt++) {
                float2 kf = *(const float2*)&Kp[(nt * 8 + g) * LDK_];
                uint32_t bf[2] = { __float_as_uint(kf.x), __float_as_uint(kf.y) };
                mma_tf32(s[nt], qf[ks], bf);
            }
        }

        // ---- online softmax (log2 domain) ----
        float rmx_lo = fmaxf(fmaxf(s[0][0], s[0][1]), fmaxf(s[1][0], s[1][1]));
        float rmx_hi = fmaxf(fmaxf(s[0][2], s[0][3]), fmaxf(s[1][2], s[1][3]));
        rmx_lo = fmaxf(rmx_lo, fmaxf(fmaxf(s[2][0], s[2][1]), fmaxf(s[3][0], s[3][1])));
        rmx_hi = fmaxf(rmx_hi, fmaxf(fmaxf(s[2][2], s[2][3]), fmaxf(s[3][2], s[3][3])));
        rmx_lo = fmaxf(rmx_lo, __shfl_xor_sync(0xffffffffu, rmx_lo, 1));
        rmx_lo = fmaxf(rmx_lo, __shfl_xor_sync(0xffffffffu, rmx_lo, 2));
        rmx_hi = fmaxf(rmx_hi, __shfl_xor_sync(0xffffffffu, rmx_hi, 1));
        rmx_hi = fmaxf(rmx_hi, __shfl_xor_sync(0xffffffffu, rmx_hi, 2));

        const float mn_lo = fmaxf(m_lo, rmx_lo);
        const float mn_hi = fmaxf(m_hi, rmx_hi);
        const float sc_lo = ex2(m_lo - mn_lo);
        const float sc_hi = ex2(m_hi - mn_hi);

        float rs_lo = 0.f, rs_hi = 0.f;
        #pragma unroll
        for (int nt = 0; nt < 4; nt++) {
            s[nt][0] = ex2(s[nt][0] - mn_lo);
            s[nt][1] = ex2(s[nt][1] - mn_lo);
            s[nt][2] = ex2(s[nt][2] - mn_hi);
            s[nt][3] = ex2(s[nt][3] - mn_hi);
            rs_lo += s[nt][0] + s[nt][1];
            rs_hi += s[nt][2] + s[nt][3];
        }
        rs_lo += __shfl_xor_sync(0xffffffffu, rs_lo, 1);
        rs_lo += __shfl_xor_sync(0xffffffffu, rs_lo, 2);
        rs_hi += __shfl_xor_sync(0xffffffffu, rs_hi, 1);
        rs_hi += __shfl_xor_sync(0xffffffffu, rs_hi, 2);

        l_lo = l_lo * sc_lo + rs_lo;   m_lo = mn_lo;
        l_hi = l_hi * sc_hi + rs_hi;   m_hi = mn_hi;

        #pragma unroll
        for (int nt = 0; nt < 8; nt++) {
            O[nt][0] *= sc_lo; O[nt][1] *= sc_lo;
            O[nt][2] *= sc_hi; O[nt][3] *= sc_hi;
        }

        // ---- store P raw (fragment-major planes, warp-private rows) ----
        #pragma unroll
        for (int nt = 0; nt < 4; nt++) {
            float* Pp = sm + PS_OFF + nt * QPL;
            Pp[r_lo * 8 + poff0] = s[nt][0];
            Pp[r_lo * 8 + poff1] = s[nt][1];
            Pp[r_hi * 8 + poff0] = s[nt][2];
            Pp[r_hi * 8 + poff1] = s[nt][3];
        }
        __syncwarp();

        // ---- O += P @ V (k = 32 rows); V read with perm'd d index ----
        #pragma unroll
        for (int ks = 0; ks < 4; ks++) {
            uint32_t pa[4];
            {
                const float* Pp = sm + PS_OFF + ks * QPL;
                float2 t0 = *(const float2*)&Pp[r_lo * 8 + tg * 2];
                float2 t1 = *(const float2*)&Pp[r_hi * 8 + tg * 2];
                pa[0] = __float_as_uint(t0.x); pa[2] = __float_as_uint(t0.y);
                pa[1] = __float_as_uint(t1.x); pa[3] = __float_as_uint(t1.y);
            }
            const float* Vp  = Vst + (ks * 8 + tg) * LDV_;
            const float* Vp4 = Vp + 4 * LDV_;
            #pragma unroll
            for (int nt = 0; nt < 8; nt++) {
                uint32_t bv[2] = { __float_as_uint(Vp[nt * 8 + pg]),
                                   __float_as_uint(Vp4[nt * 8 + pg]) };
                mma_tf32(O[nt], pa, bv);
            }
        }
    }
    #undef ISSUE_TILE

    // ---- finalize + write [B,N,D] perm8'd + tf32-rounded (for proj) ----
    const float il_lo = 1.f / l_lo;
    const float il_hi = 1.f / l_hi;
    const int n_lo = qb * QROWS + r_lo;
    const int n_hi = n_lo + 8;
    #pragma unroll
    for (int nt = 0; nt < 8; nt++) {
        const int cg = h * HD_ + nt * 8;
        float* olo = &out[((size_t)b * N_ + n_lo) * D_ + cg];
        float* ohi = &out[((size_t)b * N_ + n_hi) * D_ + cg];
        olo[poff0] = tff(O[nt][0] * il_lo);
        olo[poff1] = tff(O[nt][1] * il_lo);
        ohi[poff0] = tff(O[nt][2] * il_hi);
        ohi[poff1] = tff(O[nt][3] * il_hi);
    }
}

// ---------------------------------------------------------------------------
// Launch
// ---------------------------------------------------------------------------
extern "C" void kernel_launch(void* const* d_in, const int* in_sizes, int n_in,
                              void* d_out, int out_size)
{
    const float* x      = (const float*)d_in[0];
    const float* w_qkv  = (const float*)d_in[1];
    const float* w_proj = (const float*)d_in[2];
    const float* b_proj = (const float*)d_in[3];
    float* out = (float*)d_out;

    float *qkv, *att, *xr, *wqkvT, *wprojT;
    cudaGetSymbolAddress((void**)&qkv, g_qkv);
    cudaGetSymbolAddress((void**)&att, g_att);
    cudaGetSymbolAddress((void**)&xr, g_xr);
    cudaGetSymbolAddress((void**)&wqkvT, g_wqkvT);
    cudaGetSymbolAddress((void**)&wprojT, g_wprojT);

    cudaFuncSetAttribute(attn_tc, cudaFuncAttributeMaxDynamicSharedMemorySize, AT_SMEM);
    cudaFuncSetAttribute((const void*)gemm_ff<false, true, true>,
                         cudaFuncAttributeMaxDynamicSharedMemorySize, FF_SMEM);
    cudaFuncSetAttribute((const void*)gemm_ff<true, false, false>,
                         cudaFuncAttributeMaxDynamicSharedMemorySize, FF_SMEM);

    const float QSC = 0.18033688011112042f;   // 0.125 * log2(e)

    // 0) pre-round+perm X; transpose+round+perm weights (Q cols pre-scaled)
    round_perm<<<(M_ * D_ / 8 + 255) / 256, 256>>>(x, xr, M_ * D_ / 8);
    transpose_k<<<dim3(QKV_COLS / 32, D_ / 32), dim3(32, 8)>>>(
        w_qkv, wqkvT, D_, QKV_COLS, D_, QSC);
    transpose_k<<<dim3(D_ / 32, D_ / 32), dim3(32, 8)>>>(
        w_proj, wprojT, D_, D_, 0, 1.0f);

    // 1) QKV = Xr @ W_qkv  (rounded + perm8'd output; Q pre-scaled)
    gemm_ff<false, true, true><<<dim3(QKV_COLS / 128, M_ / 128), 256, FF_SMEM>>>(
        xr, wqkvT, nullptr, qkv, QKV_COLS, D_);

    // 2) fused flash attention -> [B,N,D] (rounded + perm8'd)
    attn_tc<<<dim3(N_ / QROWS, B_ * H_), 256, AT_SMEM>>>(qkv, att);

    // 3) OUT = ATT @ W_proj + b  (final output, standard layout)
    gemm_ff<true, false, false><<<dim3(D_ / 128, M_ / 128), 256, FF_SMEM>>>(
        att, wprojT, b_proj, out, D_, D_);
}

// round 15
// speedup vs baseline: 1.0506x; 1.0113x over previous
#include <cuda_runtime.h>
#include <math.h>
#include <stdint.h>

// ---------------------------------------------------------------------------
// Problem constants
// ---------------------------------------------------------------------------
#define B_   4
#define N_   2048
#define D_   768
#define H_   12
#define HD_  64
#define M_   (B_ * N_)             // 8192
#define QKV_COLS (3 * D_)          // 2304

// Scratch (alloc-free rule)
__device__ float g_qkv[(size_t)M_ * QKV_COLS];     // perm8 layout on d
__device__ float g_att[(size_t)M_ * D_];           // perm8 layout on d
__device__ float g_xr[(size_t)M_ * D_];            // tf32-rounded X, perm8 on k
__device__ float g_wqkvT[(size_t)QKV_COLS * D_];   // [N][K], perm8 on k
__device__ float g_wprojT[(size_t)D_ * D_];        // [N][K], perm8 on k

// perm within each 8-group: d -> (d&3)*2 + ((d>>2)&1)

// ---------------------------------------------------------------------------
// tf32 helpers (legacy mma path — harness targets sm_100 base, no tcgen05)
// ---------------------------------------------------------------------------
__device__ __forceinline__ float tff(float x) {
    float r;
    asm("{ .reg .b32 t; cvt.rna.tf32.f32 t, %1; mov.b32 %0, t; }" : "=f"(r) : "f"(x));
    return r;
}

__device__ __forceinline__ float ex2(float x) {
    float y;
    asm("ex2.approx.ftz.f32 %0, %1;" : "=f"(y) : "f"(x));
    return y;
}

__device__ __forceinline__ void mma_tf32(float* c, const uint32_t* a, const uint32_t* b) {
    asm volatile(
        "mma.sync.aligned.m16n8k8.row.col.f32.tf32.tf32.f32 "
        "{%0,%1,%2,%3}, {%4,%5,%6,%7}, {%8,%9}, {%0,%1,%2,%3};"
        : "+f"(c[0]), "+f"(c[1]), "+f"(c[2]), "+f"(c[3])
        : "r"(a[0]), "r"(a[1]), "r"(a[2]), "r"(a[3]), "r"(b[0]), "r"(b[1]));
}

__device__ __forceinline__ void cpa16(uint32_t dst, const float* src) {
    asm volatile("cp.async.ca.shared.global [%0], [%1], 16;"
                 :: "r"(dst), "l"(src) : "memory");
}
__device__ __forceinline__ void cpa_commit() {
    asm volatile("cp.async.commit_group;" ::: "memory");
}
template<int NN>
__device__ __forceinline__ void cpa_wait() {
    asm volatile("cp.async.wait_group %0;" :: "n"(NN) : "memory");
}

__device__ __forceinline__ uint32_t smem_u32(const void* p) {
    uint32_t a;
    asm("{ .reg .u64 t; cvta.to.shared.u64 t, %1; cvt.u32.u64 %0, t; }" : "=r"(a) : "l"(p));
    return a;
}

// ---------------------------------------------------------------------------
// Fused prologue: one kernel does
//   blocks [0, XB)            : round+perm X (8 floats/thread)
//   blocks [XB, XB+QB)        : transpose+round+perm w_qkv (scaled Q cols)
//   blocks [XB+QB, XB+QB+PB)  : transpose+round+perm w_proj
// ---------------------------------------------------------------------------
#define XB (M_ * D_ / 8 / 256)      // 3072
#define QB ((QKV_COLS / 32) * (D_ / 32))   // 72*24 = 1728
#define PB ((D_ / 32) * (D_ / 32))         // 576

__device__ __forceinline__ void do_transpose(
    const float* __restrict__ in, float* __restrict__ out, int K, int N,
    int nb, int kb, int qrows, float qscale, float (*t)[33], int tid)
{
    const int x = tid & 31, y = tid >> 5;
    #pragma unroll
    for (int i = 0; i < 32; i += 8)
        t[y + i][x] = in[(size_t)(kb + y + i) * N + nb + x];
    __syncthreads();
    const int k  = kb + x;
    const int kp = (k & ~7) | (((k & 3) << 1) | ((k >> 2) & 1));
    #pragma unroll
    for (int i = 0; i < 32; i += 8) {
        const int n = nb + y + i;
        const float s = (n < qrows) ? qscale : 1.0f;
        out[(size_t)n * K + kp] = tff(t[x][y + i] * s);
    }
}

__global__ __launch_bounds__(256) void prologue(
    const float* __restrict__ x, float* __restrict__ xr,
    const float* __restrict__ w_qkv, float* __restrict__ wqkvT,
    const float* __restrict__ w_proj, float* __restrict__ wprojT,
    float qscale)
{
    __shared__ float t[32][33];
    const int bid = blockIdx.x;
    const int tid = threadIdx.x;
    if (bid < XB) {
        const int i = bid * 256 + tid;
        float4 a = ((const float4*)x)[2 * i];
        float4 b = ((const float4*)x)[2 * i + 1];
        ((float4*)xr)[2 * i]     = make_float4(tff(a.x), tff(b.x), tff(a.y), tff(b.y));
        ((float4*)xr)[2 * i + 1] = make_float4(tff(a.z), tff(b.z), tff(a.w), tff(b.w));
    } else if (bid < XB + QB) {
        const int tb = bid - XB;
        const int nb = (tb % (QKV_COLS / 32)) * 32;
        const int kb = (tb / (QKV_COLS / 32)) * 32;
        do_transpose(w_qkv, wqkvT, D_, QKV_COLS, nb, kb, D_, qscale, t, tid);
    } else {
        const int tb = bid - XB - QB;
        const int nb = (tb % (D_ / 32)) * 32;
        const int kb = (tb / (D_ / 32)) * 32;
        do_transpose(w_proj, wprojT, D_, D_, nb, kb, 0, 1.0f, t, tid);
    }
}

// ---------------------------------------------------------------------------
// tf32 GEMM on perm8 inputs (unchanged from R12 win): fragment-major smem fed
// by cp.async 3-stage ring. 128x128 CTA tile, BK=32, 256 threads.
// ---------------------------------------------------------------------------
#define FF_STAGE 8256
#define FF_SMEM (3 * FF_STAGE * 4)

template<bool BIAS, bool ROUND, bool PERMOUT>
__global__ __launch_bounds__(256, 2) void gemm_ff(
    const float* __restrict__ A, const float* __restrict__ WT,
    const float* __restrict__ bias, float* __restrict__ C,
    int N, int K)
{
    extern __shared__ float smf[];
    const uint32_t sb4 = smem_u32(smf);

    const int tid  = threadIdx.x;
    const int lane = tid & 31;
    const int wid  = tid >> 5;
    const int g    = lane >> 2;
    const int tg   = lane & 3;
    const int wm   = wid & 3;
    const int wn   = wid >> 2;
    const int row0 = blockIdx.y * 128;
    const int col0 = blockIdx.x * 128;
    const int KT   = K / 32;

    float acc[2][8][4];
    #pragma unroll
    for (int mt = 0; mt < 2; mt++)
        #pragma unroll
        for (int nt = 0; nt < 8; nt++)
            #pragma unroll
            for (int i = 0; i < 4; i++) acc[mt][nt][i] = 0.f;

    const int lrow = tid >> 3;
    const int lkq  = tid & 7;
    const int ks0  = lkq >> 1;
    const int m0   = lkq & 1;
    const int kA   = 8 * ks0 + 4 * m0;

    const float* Ap = A  + (size_t)(row0 + lrow) * K + kA;
    const float* Bp = WT + (size_t)(col0 + lrow) * K + kA;

    const int dstA0 = ks0 * 1032 + lrow * 8 + 4 * m0;

    #define ISSUE_G(t_) do {                                                 \
        const uint32_t sbase_ = sb4 + ((t_) % 3) * (FF_STAGE * 4);           \
        const size_t koff_ = (size_t)(t_) * 32;                             \
        _Pragma("unroll")                                                    \
        for (int i_ = 0; i_ < 4; i_++) {                                     \
            cpa16(sbase_ + (dstA0 + i_ * 256) * 4,                           \
                  Ap + (size_t)(i_ * 32) * K + koff_);                       \
            cpa16(sbase_ + (4128 + dstA0 + i_ * 256) * 4,                    \
                  Bp + (size_t)(i_ * 32) * K + koff_);                       \
        }                                                                    \
        cpa_commit();                                                        \
    } while (0)

    ISSUE_G(0);
    if (KT > 1) ISSUE_G(1);

    for (int t = 0; t < KT; t++) {
        if (t + 1 < KT) cpa_wait<1>(); else cpa_wait<0>();
        __syncthreads();

        if (t + 2 < KT) ISSUE_G(t + 2);

        const float2* As2 = (const float2*)(smf + (t % 3) * FF_STAGE);
        const float2* Bs2 = As2 + 2064;

        #pragma unroll
        for (int ks = 0; ks < 4; ks++) {
            const float2* Ak = As2 + ks * 516;
            const float2* Bk = Bs2 + ks * 516;
            uint32_t af[2][4];
            #pragma unroll
            for (int mt = 0; mt < 2; mt++) {
                const int r = wm * 32 + mt * 16 + g;
                float2 v1 = Ak[r * 4 + tg];
                float2 v2 = Ak[(r + 8) * 4 + tg];
                af[mt][0] = __float_as_uint(v1.x);
                af[mt][1] = __float_as_uint(v2.x);
                af[mt][2] = __float_as_uint(v1.y);
                af[mt][3] = __float_as_uint(v2.y);
            }
            #pragma unroll
            for (int nt = 0; nt < 8; nt++) {
                const int c = wn * 64 + nt * 8 + g;
                float2 w = Bk[c * 4 + tg];
                uint32_t bf[2] = { __float_as_uint(w.x), __float_as_uint(w.y) };
                mma_tf32(acc[0][nt], af[0], bf);
                mma_tf32(acc[1][nt], af[1], bf);
            }
        }
    }
    #undef ISSUE_G

    const int dl = 2 * tg;
    const int p0 = ((dl & 3) << 1) + (dl >> 2);
    const int p1 = (((dl + 1) & 3) << 1) + ((dl + 1) >> 2);

    #pragma unroll
    for (int mt = 0; mt < 2; mt++) {
        const int r_lo = row0 + wm * 32 + mt * 16 + g;
        const int r_hi = r_lo + 8;
        #pragma unroll
        for (int nt = 0; nt < 8; nt++) {
            const int c = col0 + wn * 64 + nt * 8 + 2 * tg;
            float2 v0 = make_float2(acc[mt][nt][0], acc[mt][nt][1]);
            float2 v1 = make_float2(acc[mt][nt][2], acc[mt][nt][3]);
            if (BIAS) {
                float2 bb = *(const float2*)&bias[c];
                v0.x += bb.x; v0.y += bb.y;
                v1.x += bb.x; v1.y += bb.y;
            }
            if (ROUND) {
                v0.x = tff(v0.x); v0.y = tff(v0.y);
                v1.x = tff(v1.x); v1.y = tff(v1.y);
            }
            if (PERMOUT) {
                const int cg = c & ~7;
                C[(size_t)r_lo * N + cg + p0] = v0.x;
                C[(size_t)r_lo * N + cg + p1] = v0.y;
                C[(size_t)r_hi * N + cg + p0] = v1.x;
                C[(size_t)r_hi * N + cg + p1] = v1.y;
            } else {
                *(float2*)&C[(size_t)r_lo * N + c] = v0;
                *(float2*)&C[(size_t)r_hi * N + c] = v1;
            }
        }
    }
}

// ---------------------------------------------------------------------------
// Flash attention (R12 structure: 32-col KV tiles, 3-stage cp.async ring,
// perm8 inputs, Q fragments in regs, raw-P PV) + warp-uniform skip-rescale
// fast path: when no row in the warp updates its max, sc == 1.0 exactly and
// the rescale/m-update is skipped (bit-identical).
// ---------------------------------------------------------------------------
#define QPL   1032
#define PS_OFF 0
#define KS_OFF 4128
#define KS_STRIDE 2304
#define VS_OFF 11040
#define VS_STRIDE 2304
#define LDK_  72
#define LDV_  72
#define QROWS 128
#define NTILES (N_ / 32)
#define AT_SMEM ((VS_OFF + 3 * VS_STRIDE) * 4)   // 71808 B

__global__ __launch_bounds__(256, 2) void attn_tc(
    const float* __restrict__ qkv, float* __restrict__ out)
{
    extern __shared__ float sm[];
    const uint32_t sb4 = smem_u32(sm);

    const int tid  = threadIdx.x;
    const int lane = tid & 31;
    const int wid  = tid >> 5;
    const int g    = lane >> 2;
    const int tg   = lane & 3;
    const int qb   = blockIdx.x;            // 0..15
    const int bh   = blockIdx.y;            // 0..47
    const int b    = bh / H_;
    const int h    = bh % H_;

    const size_t base = (size_t)b * N_ * QKV_COLS;
    const int qoff = h * HD_;
    const int koff = D_ + h * HD_;
    const int voff = 2 * D_ + h * HD_;

    const int cr0 = tid >> 4;
    const int cd  = (tid & 15) * 4;

    const float* tp = qkv + base + (size_t)cr0 * QKV_COLS;
    const size_t TILE_STEP = (size_t)32 * QKV_COLS;

    #define ISSUE_TILE(ptr_, ss_) do {                                       \
        const float* r1_ = (ptr_) + (size_t)16 * QKV_COLS;                   \
        const uint32_t kd_ = sb4 + (KS_OFF + (ss_) * KS_STRIDE) * 4;         \
        const uint32_t vd_ = sb4 + (VS_OFF + (ss_) * VS_STRIDE) * 4;         \
        cpa16(kd_ + (cr0 * LDK_ + cd) * 4,        (ptr_) + koff + cd);       \
        cpa16(kd_ + ((cr0 + 16) * LDK_ + cd) * 4, r1_ + koff + cd);          \
        cpa16(vd_ + (cr0 * LDV_ + cd) * 4,        (ptr_) + voff + cd);       \
        cpa16(vd_ + ((cr0 + 16) * LDV_ + cd) * 4, r1_ + voff + cd);          \
        cpa_commit();                                                        \
    } while (0)

    ISSUE_TILE(tp, 0);
    ISSUE_TILE(tp + TILE_STEP, 1);
    const float* tp2 = tp + 2 * TILE_STEP;

    // ---- Q fragments to registers (perm layout: pair adjacent) ----
    const int r_lo = wid * 16 + g;
    const int r_hi = r_lo + 8;
    uint32_t qf[8][4];
    {
        const float* qlo = qkv + base + (size_t)(qb * QROWS + r_lo) * QKV_COLS + qoff;
        const float* qhi = qkv + base + (size_t)(qb * QROWS + r_hi) * QKV_COLS + qoff;
        #pragma unroll
        for (int ks = 0; ks < 8; ks++) {
            float2 q0 = *(const float2*)&qlo[8 * ks + 2 * tg];
            float2 q1 = *(const float2*)&qhi[8 * ks + 2 * tg];
            qf[ks][0] = __float_as_uint(q0.x);
            qf[ks][2] = __float_as_uint(q0.y);
            qf[ks][1] = __float_as_uint(q1.x);
            qf[ks][3] = __float_as_uint(q1.y);
        }
    }

    const int dd0 = 2 * tg, dd1 = 2 * tg + 1;
    const int poff0 = (dd0 & 3) * 2 + (dd0 >> 2);
    const int poff1 = (dd1 & 3) * 2 + (dd1 >> 2);
    const int pg = ((g & 3) << 1) | (g >> 2);

    float O[8][4];
    #pragma unroll
    for (int nt = 0; nt < 8; nt++)
        #pragma unroll
        for (int i = 0; i < 4; i++) O[nt][i] = 0.f;
    float m_lo = -INFINITY, m_hi = -INFINITY, l_lo = 0.f, l_hi = 0.f;

    int ss = 0;
    for (int t = 0; t < NTILES; t++) {
        if (t == NTILES - 1) cpa_wait<0>(); else cpa_wait<1>();
        __syncthreads();

        if (t + 2 < NTILES) {
            const int ns = (ss + 2 >= 3) ? ss - 1 : ss + 2;
            ISSUE_TILE(tp2, ns);
            tp2 += TILE_STEP;
        }

        const float* Kst = sm + KS_OFF + ss * KS_STRIDE;
        const float* Vst = sm + VS_OFF + ss * VS_STRIDE;

        // ---- S = Q @ K^T (32 cols) ----
        float s[4][4];
        #pragma unroll
        for (int nt = 0; nt < 4; nt++)
            #pragma unroll
            for (int i = 0; i < 4; i++) s[nt][i] = 0.f;

        #pragma unroll
        for (int ks = 0; ks < 8; ks++) {
            const float* Kp = Kst + 8 * ks + 2 * tg;
            #pragma unroll
            for (int nt = 0; nt < 4; nt++) {
                float2 kf = *(const float2*)&Kp[(nt * 8 + g) * LDK_];
                uint32_t bf[2] = { __float_as_uint(kf.x), __float_as_uint(kf.y) };
                mma_tf32(s[nt], qf[ks], bf);
            }
        }

        // ---- online softmax (log2 domain) with skip-rescale fast path ----
        float rmx_lo = fmaxf(fmaxf(s[0][0], s[0][1]), fmaxf(s[1][0], s[1][1]));
        float rmx_hi = fmaxf(fmaxf(s[0][2], s[0][3]), fmaxf(s[1][2], s[1][3]));
        rmx_lo = fmaxf(rmx_lo, fmaxf(fmaxf(s[2][0], s[2][1]), fmaxf(s[3][0], s[3][1])));
        rmx_hi = fmaxf(rmx_hi, fmaxf(fmaxf(s[2][2], s[2][3]), fmaxf(s[3][2], s[3][3])));
        rmx_lo = fmaxf(rmx_lo, __shfl_xor_sync(0xffffffffu, rmx_lo, 1));
        rmx_lo = fmaxf(rmx_lo, __shfl_xor_sync(0xffffffffu, rmx_lo, 2));
        rmx_hi = fmaxf(rmx_hi, __shfl_xor_sync(0xffffffffu, rmx_hi, 1));
        rmx_hi = fmaxf(rmx_hi, __shfl_xor_sync(0xffffffffu, rmx_hi, 2));

        const bool upd = (rmx_lo > m_lo) || (rmx_hi > m_hi);
        if (__any_sync(0xffffffffu, upd)) {
            // slow path: max updated somewhere in the warp
            const float mn_lo = fmaxf(m_lo, rmx_lo);
            const float mn_hi = fmaxf(m_hi, rmx_hi);
            const float sc_lo = ex2(m_lo - mn_lo);
            const float sc_hi = ex2(m_hi - mn_hi);
            l_lo *= sc_lo;  l_hi *= sc_hi;
            m_lo = mn_lo;   m_hi = mn_hi;
            #pragma unroll
            for (int nt = 0; nt < 8; nt++) {
                O[nt][0] *= sc_lo; O[nt][1] *= sc_lo;
                O[nt][2] *= sc_hi; O[nt][3] *= sc_hi;
            }
        }
        // exp + row-sum (common to both paths; on fast path m unchanged)
        float rs_lo = 0.f, rs_hi = 0.f;
        #pragma unroll
        for (int nt = 0; nt < 4; nt++) {
            s[nt][0] = ex2(s[nt][0] - m_lo);
            s[nt][1] = ex2(s[nt][1] - m_lo);
            s[nt][2] = ex2(s[nt][2] - m_hi);
            s[nt][3] = ex2(s[nt][3] - m_hi);
            rs_lo += s[nt][0] + s[nt][1];
            rs_hi += s[nt][2] + s[nt][3];
        }
        rs_lo += __shfl_xor_sync(0xffffffffu, rs_lo, 1);
        rs_lo += __shfl_xor_sync(0xffffffffu, rs_lo, 2);
        rs_hi += __shfl_xor_sync(0xffffffffu, rs_hi, 1);
        rs_hi += __shfl_xor_sync(0xffffffffu, rs_hi, 2);
        l_lo += rs_lo;
        l_hi += rs_hi;

        // ---- store P raw (fragment-major planes, warp-private rows) ----
        #pragma unroll
        for (int nt = 0; nt < 4; nt++) {
            float* Pp = sm + PS_OFF + nt * QPL;
            Pp[r_lo * 8 + poff0] = s[nt][0];
            Pp[r_lo * 8 + poff1] = s[nt][1];
            Pp[r_hi * 8 + poff0] = s[nt][2];
            Pp[r_hi * 8 + poff1] = s[nt][3];
        }
        __syncwarp();

        // ---- O += P @ V (k = 32 rows) ----
        #pragma unroll
        for (int ks = 0; ks < 4; ks++) {
            uint32_t pa[4];
            {
                const float* Pp = sm + PS_OFF + ks * QPL;
                float2 t0 = *(const float2*)&Pp[r_lo * 8 + tg * 2];
                float2 t1 = *(const float2*)&Pp[r_hi * 8 + tg * 2];
                pa[0] = __float_as_uint(t0.x); pa[2] = __float_as_uint(t0.y);
                pa[1] = __float_as_uint(t1.x); pa[3] = __float_as_uint(t1.y);
            }
            const float* Vp  = Vst + (ks * 8 + tg) * LDV_;
            const float* Vp4 = Vp + 4 * LDV_;
            #pragma unroll
            for (int nt = 0; nt < 8; nt++) {
                uint32_t bv[2] = { __float_as_uint(Vp[nt * 8 + pg]),
                                   __float_as_uint(Vp4[nt * 8 + pg]) };
                mma_tf32(O[nt], pa, bv);
            }
        }

        ss = (ss + 1 >= 3) ? 0 : ss + 1;
    }
    #undef ISSUE_TILE

    // ---- finalize + write [B,N,D] perm8'd + tf32-rounded (for proj) ----
    const float il_lo = 1.f / l_lo;
    const float il_hi = 1.f / l_hi;
    const int n_lo = qb * QROWS + r_lo;
    const int n_hi = n_lo + 8;
    #pragma unroll
    for (int nt = 0; nt < 8; nt++) {
        const int cg = h * HD_ + nt * 8;
        float* olo = &out[((size_t)b * N_ + n_lo) * D_ + cg];
        float* ohi = &out[((size_t)b * N_ + n_hi) * D_ + cg];
        olo[poff0] = tff(O[nt][0] * il_lo);
        olo[poff1] = tff(O[nt][1] * il_lo);
        ohi[poff0] = tff(O[nt][2] * il_hi);
        ohi[poff1] = tff(O[nt][3] * il_hi);
    }
}

// ---------------------------------------------------------------------------
// Launch
// ---------------------------------------------------------------------------
extern "C" void kernel_launch(void* const* d_in, const int* in_sizes, int n_in,
                              void* d_out, int out_size)
{
    const float* x      = (const float*)d_in[0];
    const float* w_qkv  = (const float*)d_in[1];
    const float* w_proj = (const float*)d_in[2];
    const float* b_proj = (const float*)d_in[3];
    float* out = (float*)d_out;

    float *qkv, *att, *xr, *wqkvT, *wprojT;
    cudaGetSymbolAddress((void**)&qkv, g_qkv);
    cudaGetSymbolAddress((void**)&att, g_att);
    cudaGetSymbolAddress((void**)&xr, g_xr);
    cudaGetSymbolAddress((void**)&wqkvT, g_wqkvT);
    cudaGetSymbolAddress((void**)&wprojT, g_wprojT);

    cudaFuncSetAttribute(attn_tc, cudaFuncAttributeMaxDynamicSharedMemorySize, AT_SMEM);
    cudaFuncSetAttribute((const void*)gemm_ff<false, true, true>,
                         cudaFuncAttributeMaxDynamicSharedMemorySize, FF_SMEM);
    cudaFuncSetAttribute((const void*)gemm_ff<true, false, false>,
                         cudaFuncAttributeMaxDynamicSharedMemorySize, FF_SMEM);

    const float QSC = 0.18033688011112042f;   // 0.125 * log2(e)

    // 0) fused prologue: round+perm X, transpose+round+perm both weights
    prologue<<<XB + QB + PB, 256>>>(x, xr, w_qkv, wqkvT, w_proj, wprojT, QSC);

    // 1) QKV = Xr @ W_qkv  (rounded + perm8'd output; Q pre-scaled)
    gemm_ff<false, true, true><<<dim3(QKV_COLS / 128, M_ / 128), 256, FF_SMEM>>>(
        xr, wqkvT, nullptr, qkv, QKV_COLS, D_);

    // 2) fused flash attention -> [B,N,D] (rounded + perm8'd)
    attn_tc<<<dim3(N_ / QROWS, B_ * H_), 256, AT_SMEM>>>(qkv, att);

    // 3) OUT = ATT @ W_proj + b  (final output, standard layout)
    gemm_ff<true, false, false><<<dim3(D_ / 128, M_ / 128), 256, FF_SMEM>>>(
        att, wprojT, b_proj, out, D_, D_);
}